// round 4
// baseline (speedup 1.0000x reference)
#include <cuda_runtime.h>
#include <cstdint>

// Problem constants: x [64,128,8,256] -> T=65536 tokens, prototypes [512,256]
#define DD   256     // feature dim
#define TM   64      // tokens per CTA
#define PT   256     // protos per tile (2 tiles cover P=512)
#define KC   64      // k per chunk (4 chunks per tile)
#define K4   (KC/4)  // float4 groups per chunk = 16
#define NTH  256
#define PMAX 512

// smem (floats):
//  xs     : TM*DD          = 16384
//  ps     : 2*K4*PT*4      = 32768   (double-buffered proto tile, [buf][k4][proto] float4)
//  pn_s   : PMAX           = 512
//  cand_d : 64*33          = 2112
//  cand_i : 64*33          = 2112 (ints)
//  best_d : 64
//  best_i : 64 (ints)
#define SMEM_FLOATS (TM*DD + 2*K4*PT*4 + PMAX + 64*33 + 64*33 + 64 + 64)
#define SMEM_BYTES  (SMEM_FLOATS * 4)

__device__ float g_pnorm[4096];

// ||p||^2 with fp64 accumulation
__global__ void pnorm_kernel(const float* __restrict__ protos, int P) {
    int p = blockIdx.x * blockDim.x + threadIdx.x;
    if (p >= P) return;
    const float4* row = reinterpret_cast<const float4*>(protos + (size_t)p * DD);
    double s = 0.0;
#pragma unroll
    for (int i = 0; i < DD / 4; i++) {
        float4 v = row[i];
        s += (double)v.x * v.x + (double)v.y * v.y + (double)v.z * v.z + (double)v.w * v.w;
    }
    g_pnorm[p] = (float)s;
}

// ---- packed-fp32 / async-copy primitives ----
__device__ __forceinline__ void ffma2(unsigned long long& d, unsigned long long a,
                                      unsigned long long b) {
    asm("fma.rn.f32x2 %0, %1, %2, %0;" : "+l"(d) : "l"(a), "l"(b));
}
__device__ __forceinline__ void lds128_2x64(unsigned long long& x, unsigned long long& y,
                                            unsigned addr) {
    asm("ld.shared.v2.u64 {%0,%1}, [%2];" : "=l"(x), "=l"(y) : "r"(addr));
}
__device__ __forceinline__ void unpack2(float& lo, float& hi, unsigned long long v) {
    asm("mov.b64 {%0,%1}, %2;" : "=f"(lo), "=f"(hi) : "l"(v));
}
__device__ __forceinline__ void cpasync16(unsigned dst, const void* src) {
    asm volatile("cp.async.cg.shared.global [%0], [%1], 16;" :: "r"(dst), "l"(src));
}
__device__ __forceinline__ void cpasync_commit() {
    asm volatile("cp.async.commit_group;" ::: "memory");
}
__device__ __forceinline__ void cpasync_wait_all() {
    asm volatile("cp.async.wait_group 0;" ::: "memory");
}

__global__ __launch_bounds__(NTH, 1)
void vq_kernel(const float* __restrict__ x,
               const float* __restrict__ protos,
               float* __restrict__ proto_out,
               float* __restrict__ resid_out,
               float* __restrict__ loss_out,
               float loss_scale) {
    extern __shared__ float sm[];
    float* xs     = sm;                          // TM*DD
    float* ps     = xs + TM * DD;                // 2*K4*PT float4s
    float* pn_s   = ps + 2 * K4 * PT * 4;        // PMAX
    float* cand_d = pn_s + PMAX;                 // 64*33
    int*   cand_i = (int*)(cand_d + 64 * 33);    // 64*33
    float* best_d = (float*)(cand_i + 64 * 33);  // 64
    int*   best_i = (int*)(best_d + 64);         // 64

    const int tid = threadIdx.x;
    const int tx  = tid & 31;    // proto lane: protos tx + 32*j
    const int ty  = tid >> 5;    // token group: tokens ty*8 .. ty*8+7
    const size_t tok0 = (size_t)blockIdx.x * TM;

    const unsigned xs_sa = (unsigned)__cvta_generic_to_shared(xs);
    const unsigned ps_sa = (unsigned)__cvta_generic_to_shared(ps);

    // ---- load X tile (64 x 256 f32 = 64KB), coalesced float4 ----
    {
        const float4* xg  = reinterpret_cast<const float4*>(x + tok0 * DD);
        float4*       xs4 = reinterpret_cast<float4*>(xs);
#pragma unroll
        for (int i = 0; i < (TM * DD / 4) / NTH; i++)
            xs4[tid + i * NTH] = xg[tid + i * NTH];
    }
#pragma unroll
    for (int i = 0; i < PMAX / NTH; i++)
        pn_s[tid + i * NTH] = g_pnorm[tid + i * NTH];
    if (tid < TM) { best_d[tid] = 3.4e38f; best_i[tid] = 0; }

    // loader mapping: thread covers (k4-quarter lk, proto bases lp+16r)
    const int lk = tid & 15;
    const int lp = tid >> 4;

    // prologue: async-load chunk 0 (tile 0, kc 0) into buf 0
#pragma unroll
    for (int r = 0; r < 16; r++) {
        int proto = lp + 16 * r;
        const float4* src = reinterpret_cast<const float4*>(protos) + (size_t)proto * (DD / 4) + lk;
        unsigned dst = ps_sa + (unsigned)(((0 * K4 + lk) * PT + proto) * 16);
        cpasync16(dst, src);
    }
    cpasync_commit();

    unsigned long long acc[8][8];   // f32x2 chunk accumulators (even/odd k chains)
    float tot[8][8];                // scalar per-tile totals
#pragma unroll
    for (int i = 0; i < 8; i++)
#pragma unroll
        for (int j = 0; j < 8; j++) { acc[i][j] = 0ull; tot[i][j] = 0.f; }

    for (int c = 0; c < 8; c++) {       // 8 chunks: tile = c>>2, kc = c&3
        const int buf = c & 1;
        cpasync_wait_all();             // chunk c resident
        __syncthreads();                // all warps done with buf (c+1)&1's old data
        if (c < 7) {                    // prefetch chunk c+1 (overlaps compute)
            const int nc = c + 1;
            const int npb = (nc >> 2) * PT;
            const int nkc = nc & 3;
            const int nbuf = nc & 1;
#pragma unroll
            for (int r = 0; r < 16; r++) {
                int proto = lp + 16 * r;
                const float4* src = reinterpret_cast<const float4*>(protos) +
                                    (size_t)(npb + proto) * (DD / 4) + nkc * K4 + lk;
                unsigned dst = ps_sa + (unsigned)(((nbuf * K4 + lk) * PT + proto) * 16);
                cpasync16(dst, src);
            }
            cpasync_commit();
        }
        const int kc = c & 3;

        // ---- mainloop: 16 k4 steps, 128 FFMA2 each ----
#pragma unroll
        for (int k4 = 0; k4 < K4; k4++) {
            unsigned long long a0[8], a1[8];
#pragma unroll
            for (int i = 0; i < 8; i++)   // warp-broadcast loads
                lds128_2x64(a0[i], a1[i],
                            xs_sa + (unsigned)((((ty * 8 + i) * DD) + kc * KC + k4 * 4) * 4));
#pragma unroll
            for (int j = 0; j < 8; j++) {
                unsigned long long b0, b1;  // coalesced: lane tx -> proto tx+32j
                lds128_2x64(b0, b1,
                            ps_sa + (unsigned)(((buf * K4 + k4) * PT + tx + 32 * j) * 16));
#pragma unroll
                for (int i = 0; i < 8; i++) {
                    ffma2(acc[i][j], a0[i], b0);
                    ffma2(acc[i][j], a1[i], b1);
                }
            }
        }

        // ---- fold chunk accumulators into scalar totals ----
#pragma unroll
        for (int i = 0; i < 8; i++)
#pragma unroll
            for (int j = 0; j < 8; j++) {
                float lo, hi; unpack2(lo, hi, acc[i][j]);
                tot[i][j] += (lo + hi);
                acc[i][j] = 0ull;
            }

        if (kc == 3) {  // tile finished: argmin partials
            const int pbase = (c >> 2) * PT;
#pragma unroll
            for (int i = 0; i < 8; i++) {
                float bd = 3.4e38f; int bi = 0x7fffffff;
#pragma unroll
                for (int j = 0; j < 8; j++) {
                    int pidx = tx + 32 * j;
                    float d = pn_s[pbase + pidx] - 2.0f * tot[i][j];
                    int gi = pbase + pidx;
                    if (d < bd || (d == bd && gi < bi)) { bd = d; bi = gi; }
                    tot[i][j] = 0.f;
                }
                cand_d[(ty * 8 + i) * 33 + tx] = bd;
                cand_i[(ty * 8 + i) * 33 + tx] = bi;
            }
            __syncthreads();
            if (tid < TM) {
                float bd = best_d[tid]; int bi = best_i[tid];
#pragma unroll
                for (int l = 0; l < 32; l++) {
                    float d = cand_d[tid * 33 + l];
                    int  id = cand_i[tid * 33 + l];
                    if (d < bd || (d == bd && id < bi)) { bd = d; bi = id; }
                }
                best_d[tid] = bd; best_i[tid] = bi;
            }
            __syncthreads();
        }
    }

    // ---- epilogue: gather proto row, write proto + residual, loss ----
    {
        int row = tid >> 2;  // 0..63
        int c0  = tid & 3;
        int bi  = best_i[row];
        const float4* pr = reinterpret_cast<const float4*>(protos + (size_t)bi * DD);
        const float4* xr = reinterpret_cast<const float4*>(xs + row * DD);
        float4* po = reinterpret_cast<float4*>(proto_out + (tok0 + row) * DD);
        float4* ro = reinterpret_cast<float4*>(resid_out + (tok0 + row) * DD);
        float ls = 0.f;
#pragma unroll
        for (int s = 0; s < 16; s++) {
            int cc = c0 + s * 4;
            float4 p  = __ldg(&pr[cc]);
            float4 xv = xr[cc];
            float4 r;
            r.x = xv.x - p.x; r.y = xv.y - p.y;
            r.z = xv.z - p.z; r.w = xv.w - p.w;
            po[cc] = p;
            ro[cc] = r;
            ls += r.x * r.x + r.y * r.y + r.z * r.z + r.w * r.w;
        }
#pragma unroll
        for (int off = 16; off > 0; off >>= 1)
            ls += __shfl_down_sync(0xffffffffu, ls, off);
        float* red = cand_d;  // reuse
        if ((tid & 31) == 0) red[tid >> 5] = ls;
        __syncthreads();
        if (tid == 0) {
            float tsum = 0.f;
#pragma unroll
            for (int w = 0; w < NTH / 32; w++) tsum += red[w];
            atomicAdd(loss_out, tsum * loss_scale);
        }
    }
}

extern "C" void kernel_launch(void* const* d_in, const int* in_sizes, int n_in,
                              void* d_out, int out_size) {
    const float* x      = (const float*)d_in[0];
    const float* protos = (const float*)d_in[1];
    const int T = in_sizes[0] / DD;   // 65536
    const int P = in_sizes[1] / DD;   // 512

    float* proto_out = (float*)d_out;
    float* resid_out = proto_out + (size_t)T * DD;
    float* loss_out  = resid_out + (size_t)T * DD;

    cudaMemsetAsync(loss_out, 0, sizeof(float), 0);

    pnorm_kernel<<<(P + 255) / 256, 256>>>(protos, P);

    cudaFuncSetAttribute(vq_kernel, cudaFuncAttributeMaxDynamicSharedMemorySize, SMEM_BYTES);
    float loss_scale = 1.25f / ((float)T * (float)DD);
    vq_kernel<<<T / TM, NTH, SMEM_BYTES>>>(x, protos, proto_out, resid_out,
                                           loss_out, loss_scale);
}

// round 13
// speedup vs baseline: 2.2635x; 2.2635x over previous
#include <cuda_runtime.h>
#include <cuda_fp16.h>
#include <cstdint>

// x [64,128,8,256] -> T=65536 tokens; prototypes [512,256]; out = proto|resid|loss
#define DD      256
#define M_CTA   128     // tokens per CTA
#define NTT     32      // protos per N-tile
#define NTILES  16      // 16*32 = 512 protos
#define NTH     256
#define XPAD    264     // halves per padded row
#define ROWB    528     // bytes per padded row (16B-aligned, conflict-free)

// smem byte offsets
#define XHI_OFF 0                // 128 x 264 fp16
#define XLO_OFF 67584
#define PB_OFF  135168           // 2 bufs x (hi 16896 + lo 16896)
#define PB_BUF  33792
#define PB_LO   16896
#define PN_OFF  202752           // 512 f32
#define SB_OFF  204800           // best_i[128]
#define RED_OFF 205312           // 8 floats
#define SMEM_TOTAL 205344

__device__ __half g_phi[512 * 256];
__device__ __half g_plo[512 * 256];
__device__ float  g_pnorm[512];

static __device__ __forceinline__ uint32_t s2u(const void* p) {
    uint32_t a;
    asm("{ .reg .u64 t; cvta.to.shared.u64 t, %1; cvt.u32.u64 %0, t; }" : "=r"(a) : "l"(p));
    return a;
}
static __device__ __forceinline__ void cpa16(uint32_t dst, const void* src) {
    asm volatile("cp.async.cg.shared.global [%0], [%1], 16;" :: "r"(dst), "l"(src));
}
#define LDSM4(r0, r1, r2, r3, addr) asm volatile( \
    "ldmatrix.sync.aligned.m8n8.x4.shared.b16 {%0,%1,%2,%3}, [%4];" \
    : "=r"(r0), "=r"(r1), "=r"(r2), "=r"(r3) : "r"(addr))
// B tile is [n][k] with k contiguous == col-major kxn -> NON-trans ldmatrix
#define LDSM2(r0, r1, addr) asm volatile( \
    "ldmatrix.sync.aligned.m8n8.x2.shared.b16 {%0,%1}, [%2];" \
    : "=r"(r0), "=r"(r1) : "r"(addr))
#define MMA16816(d, a0, a1, a2, a3, b0, b1) asm volatile( \
    "mma.sync.aligned.m16n8k16.row.col.f32.f16.f16.f32 " \
    "{%0,%1,%2,%3}, {%4,%5,%6,%7}, {%8,%9}, {%0,%1,%2,%3};" \
    : "+f"((d)[0]), "+f"((d)[1]), "+f"((d)[2]), "+f"((d)[3]) \
    : "r"(a0), "r"(a1), "r"(a2), "r"(a3), "r"(b0), "r"(b1))

// ---- prep kernels ----
__global__ void pnorm_kernel(const float* __restrict__ protos) {
    int p = blockIdx.x * blockDim.x + threadIdx.x;
    if (p >= 512) return;
    const float4* row = reinterpret_cast<const float4*>(protos + (size_t)p * DD);
    double s = 0.0;
#pragma unroll
    for (int i = 0; i < DD / 4; i++) {
        float4 v = row[i];
        s += (double)v.x * v.x + (double)v.y * v.y + (double)v.z * v.z + (double)v.w * v.w;
    }
    g_pnorm[p] = (float)s;
}
__global__ void psplit_kernel(const float* __restrict__ protos) {
    int i = blockIdx.x * blockDim.x + threadIdx.x;   // 0..131071
    float v = protos[i];
    __half h = __float2half(v);
    g_phi[i] = h;
    g_plo[i] = __float2half((v - __half2float(h)) * 2048.0f);
}

// fill B tile t (protos t*32..t*32+31, hi+lo) into buf t&1
static __device__ __forceinline__ void fill_b(uint32_t sb, int t, int tid) {
#pragma unroll
    for (int j = 0; j < 8; j++) {
        int u = tid + j * NTH;                 // 0..2047
        int m = u >> 10, rem = u & 1023;
        int row = rem >> 5, ch = rem & 31;     // 32 x 16B chunks per row
        const __half* src = (m ? g_plo : g_phi) + (size_t)(t * NTT + row) * DD + ch * 8;
        uint32_t dst = sb + PB_OFF + (uint32_t)((t & 1) * PB_BUF + m * PB_LO +
                                                row * ROWB + ch * 16);
        cpa16(dst, src);
    }
    asm volatile("cp.async.commit_group;" ::: "memory");
}

__global__ __launch_bounds__(NTH, 1)
void vq_hmma(const float* __restrict__ x,
             const float* __restrict__ protos,
             float* __restrict__ proto_out,
             float* __restrict__ resid_out,
             float* __restrict__ loss_out,
             float loss_scale) {
    extern __shared__ char sm[];
    const uint32_t sb = s2u(sm);
    const int tid = threadIdx.x, wid = tid >> 5, lid = tid & 31;
    const int g = lid >> 2, tg = lid & 3;
    const size_t tok0 = (size_t)blockIdx.x * M_CTA;
    float* pn = (float*)(sm + PN_OFF);
    int*   sbest = (int*)(sm + SB_OFF);

    // prologue: start streaming tile 0 (overlaps X split)
    fill_b(sb, 0, tid);

#pragma unroll
    for (int i = 0; i < 2; i++) pn[tid + i * NTH] = g_pnorm[tid + i * NTH];

    // ---- X load + fp16 split into padded rows ----
    const float4* xg4 = reinterpret_cast<const float4*>(x + tok0 * DD);
#pragma unroll
    for (int i = 0; i < (M_CTA * DD / 4) / NTH; i++) {   // 32 iters
        int idx = tid + i * NTH;
        int row = idx >> 6, col = (idx & 63) * 4;
        float4 v = xg4[idx];
        __half h0 = __float2half(v.x), h1 = __float2half(v.y),
               h2 = __float2half(v.z), h3 = __float2half(v.w);
        __half l0 = __float2half((v.x - __half2float(h0)) * 2048.0f);
        __half l1 = __float2half((v.y - __half2float(h1)) * 2048.0f);
        __half l2 = __float2half((v.z - __half2float(h2)) * 2048.0f);
        __half l3 = __float2half((v.w - __half2float(h3)) * 2048.0f);
        uint32_t off = (uint32_t)(row * ROWB + col * 2);
        *reinterpret_cast<__half2*>(sm + XHI_OFF + off)     = __halves2half2(h0, h1);
        *reinterpret_cast<__half2*>(sm + XHI_OFF + off + 4) = __halves2half2(h2, h3);
        *reinterpret_cast<__half2*>(sm + XLO_OFF + off)     = __halves2half2(l0, l1);
        *reinterpret_cast<__half2*>(sm + XLO_OFF + off + 4) = __halves2half2(l2, l3);
    }

    float bd0 = 3.4e38f, bd1 = 3.4e38f; int bi0 = 0, bi1 = 0;

    // ldmatrix address prep
    const int ar = lid & 15, ah = lid >> 4;                 // A: rows, k-half
    const uint32_t aoff = (uint32_t)((wid * 16 + ar) * ROWB + ah * 16);
    const uint32_t ahi_base = sb + XHI_OFF + aoff;
    const uint32_t alo_base = sb + XLO_OFF + aoff;
    const int bn = lid & 7, bhh = (lid >> 3) & 1;           // B: n-row, k-half
    const uint32_t boff = (uint32_t)(bn * ROWB + bhh * 16);

    for (int t = 0; t < NTILES; t++) {
        const int buf = t & 1;
        if (t + 1 < NTILES) {
            fill_b(sb, t + 1, tid);                         // into buf^1 (freed at end of t-1)
            asm volatile("cp.async.wait_group 1;" ::: "memory");   // tile t resident
        } else {
            asm volatile("cp.async.wait_group 0;" ::: "memory");
        }
        __syncthreads();   // tile t visible to all; X ready (t==0)

        float d1[4][4], d2[4][4];
#pragma unroll
        for (int nf = 0; nf < 4; nf++)
#pragma unroll
            for (int q = 0; q < 4; q++) { d1[nf][q] = 0.f; d2[nf][q] = 0.f; }

        const uint32_t pbh = sb + PB_OFF + (uint32_t)(buf * PB_BUF) + boff;
        const uint32_t pbl = pbh + PB_LO;
#pragma unroll
        for (int k = 0; k < 16; k++) {
            uint32_t xh0, xh1, xh2, xh3, xl0, xl1, xl2, xl3;
            LDSM4(xh0, xh1, xh2, xh3, ahi_base + k * 32);
            LDSM4(xl0, xl1, xl2, xl3, alo_base + k * 32);
#pragma unroll
            for (int nf = 0; nf < 4; nf++) {
                uint32_t ph0, ph1, pl0, pl1;
                LDSM2(ph0, ph1, pbh + (uint32_t)(nf * 8 * ROWB) + k * 32);
                LDSM2(pl0, pl1, pbl + (uint32_t)(nf * 8 * ROWB) + k * 32);
                MMA16816(d1[nf], xh0, xh1, xh2, xh3, ph0, ph1);
                MMA16816(d2[nf], xh0, xh1, xh2, xh3, pl0, pl1);
                MMA16816(d2[nf], xl0, xl1, xl2, xl3, ph0, ph1);
            }
        }

        // argmin update (lane owns rows g, g+8; cols tg*2, tg*2+1 per n-frag)
#pragma unroll
        for (int nf = 0; nf < 4; nf++) {
            int n0 = t * NTT + nf * 8 + tg * 2;
            float p0 = pn[n0], p1 = pn[n0 + 1];
            float s0 = d1[nf][0] + d2[nf][0] * (1.0f / 2048.0f);
            float s1 = d1[nf][1] + d2[nf][1] * (1.0f / 2048.0f);
            float s2 = d1[nf][2] + d2[nf][2] * (1.0f / 2048.0f);
            float s3 = d1[nf][3] + d2[nf][3] * (1.0f / 2048.0f);
            float e0 = p0 - 2.0f * s0, e1 = p1 - 2.0f * s1;
            float e2 = p0 - 2.0f * s2, e3 = p1 - 2.0f * s3;
            if (e0 < bd0) { bd0 = e0; bi0 = n0; }
            if (e1 < bd0) { bd0 = e1; bi0 = n0 + 1; }
            if (e2 < bd1) { bd1 = e2; bi1 = n0; }
            if (e3 < bd1) { bd1 = e3; bi1 = n0 + 1; }
        }
        __syncthreads();   // all warps done with buf before t+1 refills the other buf
    }

    // reduce best across the 4 lanes sharing each row (tg = 0..3)
#pragma unroll
    for (int off = 1; off <= 2; off <<= 1) {
        float od = __shfl_xor_sync(0xffffffffu, bd0, off);
        int   oi = __shfl_xor_sync(0xffffffffu, bi0, off);
        if (od < bd0 || (od == bd0 && oi < bi0)) { bd0 = od; bi0 = oi; }
        od = __shfl_xor_sync(0xffffffffu, bd1, off);
        oi = __shfl_xor_sync(0xffffffffu, bi1, off);
        if (od < bd1 || (od == bd1 && oi < bi1)) { bd1 = od; bi1 = oi; }
    }
    if (tg == 0) {
        sbest[wid * 16 + g]     = bi0;
        sbest[wid * 16 + 8 + g] = bi1;
    }
    __syncthreads();

    // ---- epilogue: gather proto rows, write proto + residual, loss ----
    float ls = 0.f;
    {
        const float4* pg = reinterpret_cast<const float4*>(protos);
        float4* po = reinterpret_cast<float4*>(proto_out + tok0 * DD);
        float4* ro = reinterpret_cast<float4*>(resid_out + tok0 * DD);
#pragma unroll 4
        for (int rg = 0; rg < 16; rg++) {
            int row = wid * 16 + rg;
            int pb = sbest[row] * (DD / 4);
#pragma unroll
            for (int h = 0; h < 2; h++) {
                int cc = lid + h * 32;
                float4 p  = __ldg(&pg[pb + cc]);
                float4 xv = __ldg(&xg4[row * (DD / 4) + cc]);
                float4 r;
                r.x = xv.x - p.x; r.y = xv.y - p.y;
                r.z = xv.z - p.z; r.w = xv.w - p.w;
                po[row * (DD / 4) + cc] = p;
                ro[row * (DD / 4) + cc] = r;
                ls += r.x * r.x + r.y * r.y + r.z * r.z + r.w * r.w;
            }
        }
    }
#pragma unroll
    for (int off = 16; off > 0; off >>= 1)
        ls += __shfl_down_sync(0xffffffffu, ls, off);
    float* red = (float*)(sm + RED_OFF);
    if (lid == 0) red[wid] = ls;
    __syncthreads();
    if (tid == 0) {
        float t = 0.f;
#pragma unroll
        for (int w = 0; w < 8; w++) t += red[w];
        atomicAdd(loss_out, t * loss_scale);
    }
}

extern "C" void kernel_launch(void* const* d_in, const int* in_sizes, int n_in,
                              void* d_out, int out_size) {
    const float* x      = (const float*)d_in[0];
    const float* protos = (const float*)d_in[1];
    const int T = in_sizes[0] / DD;   // 65536

    float* proto_out = (float*)d_out;
    float* resid_out = proto_out + (size_t)T * DD;
    float* loss_out  = resid_out + (size_t)T * DD;

    cudaMemsetAsync(loss_out, 0, sizeof(float), 0);
    pnorm_kernel<<<2, 256>>>(protos);
    psplit_kernel<<<512, 256>>>(protos);

    cudaFuncSetAttribute(vq_hmma, cudaFuncAttributeMaxDynamicSharedMemorySize, SMEM_TOTAL);
    float loss_scale = 1.25f / ((float)T * (float)DD);
    vq_hmma<<<T / M_CTA, NTH, SMEM_TOTAL>>>(x, protos, proto_out, resid_out,
                                            loss_out, loss_scale);
}